// round 1
// baseline (speedup 1.0000x reference)
#include <cuda_runtime.h>
#include <cstdint>

#define NN 100000
#define EE 3200000
#define CC 32
#define LL 4
#define GG 512
#define XDIM 8
#define EDIM 4

#define QSTEP 0.0009765625f   // 2^-10
#define QINV  1024.0f
#define QMAXV (32.0f - 0.0009765625f)
#define QMINV (-32.0f)
#define BN_EPS_F 1e-5f
#define GEN_EPS_F 1e-7f
#define LOG2E_F 1.4426950408889634f

// ---------------- scratch (device globals; no allocation allowed) -------------
__device__ float d_h [NN * CC];            // 12.8 MB node features
__device__ float d_h2[NN * CC];            // 12.8 MB h + agg
__device__ short d_eq[(size_t)EE * CC];    // 204.8 MB CSR-permuted quantized edge features
__device__ int   d_srcp[EE];               // 12.8 MB CSR-permuted src ids
__device__ int   d_deg[NN];
__device__ int   d_rowptr[NN + 1];
__device__ int   d_wp[NN];
__device__ int   d_bsum[128];
__device__ int   d_boff[128];
__device__ float d_pool[GG * CC];
__device__ float d_cntf[GG];

// ---------------- helpers ------------------------------------------------------
__device__ __forceinline__ float qf(float x) {
    // ap_fixed<16,6> fake quant: round-half-even (rintf) then clip. Matches jnp.round.
    float y = rintf(x * QINV) * QSTEP;
    return fminf(fmaxf(y, QMINV), QMAXV);
}

__device__ __forceinline__ float ex2f(float x) {
    float y;
    asm("ex2.approx.f32 %0, %1;" : "=f"(y) : "f"(x));
    return y;
}

// ---------------- init ---------------------------------------------------------
__global__ void k_zero() {
    int i = blockIdx.x * blockDim.x + threadIdx.x;
    if (i < NN) d_deg[i] = 0;
    if (i < GG * CC) d_pool[i] = 0.0f;
}

// ---------------- node encoder: h = bn(qlin(x, W_node, b_node)) ----------------
__global__ void k_node_enc(const float* __restrict__ x,
                           const float* __restrict__ Wn,
                           const float* __restrict__ bn_,
                           const float* __restrict__ g,
                           const float* __restrict__ b,
                           const float* __restrict__ m,
                           const float* __restrict__ v) {
    __shared__ float Ws[XDIM * CC];
    __shared__ float bs[CC], As[CC], Ds[CC];
    int tid = threadIdx.x;
    if (tid < XDIM * CC) Ws[tid] = qf(Wn[tid]);
    if (tid < CC) {
        bs[tid] = qf(bn_[tid]);
        float rs = rsqrtf(v[tid] + BN_EPS_F);
        float a = g[tid] * rs;
        As[tid] = a;
        Ds[tid] = b[tid] - m[tid] * a;
    }
    __syncthreads();
    int node = blockIdx.x * blockDim.x + tid;
    if (node >= NN) return;
    const float4* xp = (const float4*)(x + node * XDIM);
    float4 a0 = xp[0], a1 = xp[1];
    float xq[XDIM];
    xq[0] = qf(a0.x); xq[1] = qf(a0.y); xq[2] = qf(a0.z); xq[3] = qf(a0.w);
    xq[4] = qf(a1.x); xq[5] = qf(a1.y); xq[6] = qf(a1.z); xq[7] = qf(a1.w);
    #pragma unroll
    for (int c = 0; c < CC; c++) {
        float acc = bs[c];
        #pragma unroll
        for (int k = 0; k < XDIM; k++) acc = fmaf(xq[k], Ws[k * CC + c], acc);
        float hq = qf(acc);
        d_h[node * CC + c] = fmaf(As[c], hq, Ds[c]);
    }
}

// ---------------- CSR build ----------------------------------------------------
__global__ void k_hist(const int* __restrict__ ei) {
    int e = blockIdx.x * blockDim.x + threadIdx.x;
    if (e < EE) atomicAdd(&d_deg[ei[EE + e]], 1);
}

#define SCAN_NB 98  // ceil(100000/1024)
__global__ void k_scan1() {
    __shared__ int sh[1024];
    int tid = threadIdx.x;
    int i = blockIdx.x * 1024 + tid;
    int v = (i < NN) ? d_deg[i] : 0;
    sh[tid] = v;
    __syncthreads();
    for (int o = 1; o < 1024; o <<= 1) {
        int t = (tid >= o) ? sh[tid - o] : 0;
        __syncthreads();
        sh[tid] += t;
        __syncthreads();
    }
    if (i < NN) d_rowptr[i] = sh[tid] - v;          // block-local exclusive
    if (tid == 1023) d_bsum[blockIdx.x] = sh[1023];
}
__global__ void k_scan2() {
    if (threadIdx.x == 0) {
        int run = 0;
        for (int bb = 0; bb < SCAN_NB; bb++) { d_boff[bb] = run; run += d_bsum[bb]; }
    }
}
__global__ void k_scan3() {
    int tid = threadIdx.x;
    int i = blockIdx.x * 1024 + tid;
    if (i < NN) {
        int r = d_rowptr[i] + d_boff[blockIdx.x];
        d_rowptr[i] = r;
        d_wp[i] = r;
    }
    if (i == 0) d_rowptr[NN] = EE;
}

// ---------------- edge encoder + CSR scatter ------------------------------------
// e_q = q(q(edge_attr) @ q(W_edge) + q(b_edge)) stored as int16 (exact), permuted by dst.
__global__ void k_edge_enc(const float* __restrict__ ea,
                           const float* __restrict__ We,
                           const float* __restrict__ be,
                           const int* __restrict__ ei) {
    __shared__ float Ws[EDIM * CC];
    __shared__ float bs[CC];
    int tid = threadIdx.x;
    if (tid < EDIM * CC) Ws[tid] = qf(We[tid]);
    if (tid < CC) bs[tid] = qf(be[tid]);
    __syncthreads();
    int e = blockIdx.x * blockDim.x + tid;
    if (e >= EE) return;
    float4 a = ((const float4*)ea)[e];
    float x0 = qf(a.x), x1 = qf(a.y), x2 = qf(a.z), x3 = qf(a.w);
    unsigned int us[16];
    #pragma unroll
    for (int c = 0; c < CC; c += 2) {
        float acc0 = bs[c], acc1 = bs[c + 1];
        acc0 = fmaf(x0, Ws[0 * CC + c], acc0);
        acc0 = fmaf(x1, Ws[1 * CC + c], acc0);
        acc0 = fmaf(x2, Ws[2 * CC + c], acc0);
        acc0 = fmaf(x3, Ws[3 * CC + c], acc0);
        acc1 = fmaf(x0, Ws[0 * CC + c + 1], acc1);
        acc1 = fmaf(x1, Ws[1 * CC + c + 1], acc1);
        acc1 = fmaf(x2, Ws[2 * CC + c + 1], acc1);
        acc1 = fmaf(x3, Ws[3 * CC + c + 1], acc1);
        int k0 = (int)fminf(fmaxf(rintf(acc0 * QINV), -32768.0f), 32767.0f);
        int k1 = (int)fminf(fmaxf(rintf(acc1 * QINV), -32768.0f), 32767.0f);
        us[c >> 1] = (unsigned)(k0 & 0xFFFF) | ((unsigned)k1 << 16);
    }
    int src = ei[e];
    int dst = ei[EE + e];
    int pos = atomicAdd(&d_wp[dst], 1);
    d_srcp[pos] = src;
    uint4* o = (uint4*)(d_eq + (size_t)pos * CC);
    uint4 v0 = make_uint4(us[0],  us[1],  us[2],  us[3]);
    uint4 v1 = make_uint4(us[4],  us[5],  us[6],  us[7]);
    uint4 v2 = make_uint4(us[8],  us[9],  us[10], us[11]);
    uint4 v3 = make_uint4(us[12], us[13], us[14], us[15]);
    __stcs(o + 0, v0); __stcs(o + 1, v1); __stcs(o + 2, v2); __stcs(o + 3, v3);
}

// ---------------- GENConv softmax aggregation (online, one pass) ----------------
// warp per node, lane per channel. h2 = h + softmax-agg(relu(h[src]+e)+eps)
__global__ void k_agg(const float* __restrict__ t, int l,
                      const float* __restrict__ bg, const float* __restrict__ bb,
                      const float* __restrict__ bm, const float* __restrict__ bv) {
    int lane = threadIdx.x & 31;
    int warp = threadIdx.x >> 5;
    int node = blockIdx.x * 8 + warp;
    if (node >= NN) return;

    float rs = rsqrtf(bv[lane] + BN_EPS_F);
    float ga = bg[lane] * rs;
    float A = QSTEP * ga;                      // e = A*k + D  (BN folded onto int16)
    float D = bb[lane] - bm[lane] * ga;
    float tl2 = t[l] * LOG2E_F;                // work in log2 domain: one EX2 per edge

    int p0 = d_rowptr[node], p1 = d_rowptr[node + 1];
    float mxl = -3.402823466e38f;
    float den = 0.0f, num = 0.0f;
    const short* eqp = d_eq + (size_t)p0 * CC + lane;

    for (int p = p0; p < p1; ++p) {
        int   src = __ldcs(d_srcp + p);
        short kv  = __ldcs(eqp);
        eqp += CC;
        float hs  = __ldg(d_h + src * CC + lane);
        float ev  = fmaf((float)kv, A, D);
        float m   = fmaxf(hs + ev, 0.0f) + GEN_EPS_F;
        float sl  = m * tl2;
        float dd  = sl - mxl;
        float ex  = ex2f(-fabsf(dd));          // exp2 of the non-max side
        bool  up  = dd > 0.0f;
        float r   = up ? ex : 1.0f;            // rescale old accumulators
        float e1  = up ? 1.0f : ex;            // weight of the new element
        den = fmaf(den, r, e1);
        num = fmaf(num, r, e1 * m);
        mxl = fmaxf(mxl, sl);
    }
    float agg = num / fmaxf(den, 1e-16f);
    int idx = node * CC + lane;
    d_h2[idx] = d_h[idx] + agg;
}

// ---------------- per-layer quantized MLP + residual ----------------------------
__global__ void __launch_bounds__(128) k_mlp(int l,
        const float* __restrict__ W1, const float* __restrict__ b1,
        const float* __restrict__ g1, const float* __restrict__ bb1,
        const float* __restrict__ m1, const float* __restrict__ v1,
        const float* __restrict__ W2, const float* __restrict__ b2) {
    __shared__ float w1s[CC * 2 * CC];   // 32x64
    __shared__ float w2s[2 * CC * CC];   // 64x32
    __shared__ float b1s[2 * CC], a1s[2 * CC], d1s[2 * CC], b2s[CC];
    int tid = threadIdx.x;
    const float* W1l = W1 + l * CC * 2 * CC;
    const float* W2l = W2 + l * 2 * CC * CC;
    for (int i = tid; i < CC * 2 * CC; i += 128) {
        w1s[i] = qf(W1l[i]);
        w2s[i] = qf(W2l[i]);
    }
    if (tid < 2 * CC) {
        b1s[tid] = qf(b1[l * 2 * CC + tid]);
        float rsv = rsqrtf(v1[l * 2 * CC + tid] + BN_EPS_F);
        float a = g1[l * 2 * CC + tid] * rsv;
        a1s[tid] = a;
        d1s[tid] = bb1[l * 2 * CC + tid] - m1[l * 2 * CC + tid] * a;
    }
    if (tid < CC) b2s[tid] = qf(b2[l * CC + tid]);
    __syncthreads();

    int node = blockIdx.x * 128 + tid;
    if (node >= NN) return;

    float xq[CC];
    const float4* hp = (const float4*)(d_h2 + node * CC);
    #pragma unroll
    for (int i = 0; i < 8; i++) {
        float4 t4 = hp[i];
        xq[4 * i + 0] = qf(t4.x); xq[4 * i + 1] = qf(t4.y);
        xq[4 * i + 2] = qf(t4.z); xq[4 * i + 3] = qf(t4.w);
    }
    float acc2[CC];
    #pragma unroll
    for (int c = 0; c < CC; c++) acc2[c] = b2s[c];

    for (int j = 0; j < 2 * CC; j++) {
        float a = b1s[j];
        #pragma unroll
        for (int k = 0; k < CC; k++) a = fmaf(xq[k], w1s[k * 2 * CC + j], a);
        float z1 = qf(a);
        float zr = qf(fmaxf(fmaf(a1s[j], z1, d1s[j]), 0.0f));
        #pragma unroll
        for (int c = 0; c < CC; c++) acc2[c] = fmaf(zr, w2s[j * CC + c], acc2[c]);
    }
    const float4* ip = (const float4*)(d_h + node * CC);
    float4* op = (float4*)(d_h + node * CC);
    #pragma unroll
    for (int c = 0; c < CC; c += 4) {
        float4 id4 = ip[c >> 2];
        float4 o;
        o.x = qf(acc2[c + 0]) + id4.x;
        o.y = qf(acc2[c + 1]) + id4.y;
        o.z = qf(acc2[c + 2]) + id4.z;
        o.w = qf(acc2[c + 3]) + id4.w;
        op[c >> 2] = o;
    }
}

// ---------------- global mean pool ----------------------------------------------
__global__ void k_pool(const int* __restrict__ batch) {
    int lane = threadIdx.x & 31;
    int w = (blockIdx.x * blockDim.x + threadIdx.x) >> 5;
    const int CHUNK = 128;
    int i0 = w * CHUNK;
    if (i0 >= NN) return;
    int i1 = min(i0 + CHUNK, NN);
    int cur = batch[i0];
    float acc = 0.0f;
    for (int i = i0; i < i1; i++) {
        int g = batch[i];
        float val = d_h[i * CC + lane];
        if (g != cur) {
            atomicAdd(&d_pool[cur * CC + lane], acc);
            acc = 0.0f;
            cur = g;
        }
        acc += val;
    }
    atomicAdd(&d_pool[cur * CC + lane], acc);
}

__global__ void k_cnt(const int* __restrict__ batch) {
    int g = blockIdx.x * blockDim.x + threadIdx.x;
    if (g >= GG) return;
    int lo0 = 0, hi0 = NN;
    while (lo0 < hi0) { int mid = (lo0 + hi0) >> 1; if (batch[mid] < g) lo0 = mid + 1; else hi0 = mid; }
    int lo1 = lo0, hi1 = NN;
    while (lo1 < hi1) { int mid = (lo1 + hi1) >> 1; if (batch[mid] < g + 1) lo1 = mid + 1; else hi1 = mid; }
    d_cntf[g] = (float)(lo1 - lo0);
}

__global__ void k_final(const float* __restrict__ Wo, const float* __restrict__ bo,
                        float* __restrict__ out) {
    __shared__ float wq[CC];
    int tid = threadIdx.x;
    if (tid < CC) wq[tid] = qf(Wo[tid]);
    __syncthreads();
    int g = blockIdx.x * blockDim.x + tid;
    if (g >= GG) return;
    float cnt = fmaxf(d_cntf[g], 1.0f);
    float acc = qf(bo[0]);
    #pragma unroll
    for (int c = 0; c < CC; c++) {
        float pm = d_pool[g * CC + c] / cnt;
        acc = fmaf(qf(pm), wq[c], acc);
    }
    float o = qf(acc);
    float s = 1.0f / (1.0f + expf(-o));
    out[g] = qf(s);
}

// ---------------- launch ---------------------------------------------------------
extern "C" void kernel_launch(void* const* d_in, const int* in_sizes, int n_in,
                              void* d_out, int out_size) {
    const float* x    = (const float*)d_in[0];
    const float* ea   = (const float*)d_in[1];
    const float* Wn   = (const float*)d_in[2];
    const float* bn_  = (const float*)d_in[3];
    const float* We   = (const float*)d_in[4];
    const float* be   = (const float*)d_in[5];
    const float* bnng = (const float*)d_in[6];
    const float* bnnb = (const float*)d_in[7];
    const float* bnnm = (const float*)d_in[8];
    const float* bnnv = (const float*)d_in[9];
    const float* bneg = (const float*)d_in[10];
    const float* bneb = (const float*)d_in[11];
    const float* bnem = (const float*)d_in[12];
    const float* bnev = (const float*)d_in[13];
    const float* t    = (const float*)d_in[14];
    const float* W1   = (const float*)d_in[15];
    const float* b1   = (const float*)d_in[16];
    const float* g1   = (const float*)d_in[17];
    const float* bb1  = (const float*)d_in[18];
    const float* m1   = (const float*)d_in[19];
    const float* v1   = (const float*)d_in[20];
    const float* W2   = (const float*)d_in[21];
    const float* b2   = (const float*)d_in[22];
    const float* Wo   = (const float*)d_in[23];
    const float* bo   = (const float*)d_in[24];
    const int*   ei   = (const int*)d_in[25];
    const int*   batch= (const int*)d_in[26];
    float* out = (float*)d_out;

    k_zero<<<(NN + 255) / 256, 256>>>();
    k_node_enc<<<(NN + 255) / 256, 256>>>(x, Wn, bn_, bnng, bnnb, bnnm, bnnv);
    k_hist<<<(EE + 255) / 256, 256>>>(ei);
    k_scan1<<<SCAN_NB, 1024>>>();
    k_scan2<<<1, 32>>>();
    k_scan3<<<SCAN_NB, 1024>>>();
    k_edge_enc<<<(EE + 255) / 256, 256>>>(ea, We, be, ei);

    for (int l = 0; l < LL; l++) {
        k_agg<<<(NN + 7) / 8, 256>>>(t, l, bneg, bneb, bnem, bnev);
        k_mlp<<<(NN + 127) / 128, 128>>>(l, W1, b1, g1, bb1, m1, v1, W2, b2);
    }

    k_pool<<<98, 256>>>(batch);
    k_cnt<<<(GG + 255) / 256, 256>>>(batch);
    k_final<<<(GG + 255) / 256, 256>>>(Wo, bo, out);
}